// round 1
// baseline (speedup 1.0000x reference)
#include <cuda_runtime.h>
#include <math.h>

// Problem constants
#define B_TOTAL 32768
#define P_DIM   128
#define X_DIM   30
#define Y_DIM   30
#define F_DIM   6
#define CELLS   (X_DIM * Y_DIM)   // 900
#define T_INV   (1.0f / 0.001f)

// Precomputed softmax-weighted value per grid cell.
__device__ float g_S[CELLS];

// One block per cell (900 blocks), 128 threads = P.
// v_p = dot(succ_feats[p, cell, :], w); S[cell] = sum_p softmax(v_p/T) * v_p
__global__ void precompute_S_kernel(const float* __restrict__ succ,
                                    const float* __restrict__ w) {
    const int cell = blockIdx.x;
    const int p = threadIdx.x;

    __shared__ float ws[F_DIM];
    if (p < F_DIM) ws[p] = w[p];
    __syncthreads();

    const float* base = succ + (size_t)p * (CELLS * F_DIM) + (size_t)cell * F_DIM;
    float v = 0.0f;
#pragma unroll
    for (int f = 0; f < F_DIM; ++f) v += base[f] * ws[f];

    const float x = v / 0.001f;   // match reference vs / T

    // ---- block max of x ----
    __shared__ float red[P_DIM];
    red[p] = x;
    __syncthreads();
#pragma unroll
    for (int s = P_DIM / 2; s > 0; s >>= 1) {
        if (p < s) red[p] = fmaxf(red[p], red[p + s]);
        __syncthreads();
    }
    const float mx = red[0];
    __syncthreads();

    const float e = expf(x - mx);

    // ---- block sum of e and e*v ----
    __shared__ float red2[P_DIM];
    red[p]  = e;
    red2[p] = e * v;
    __syncthreads();
#pragma unroll
    for (int s = P_DIM / 2; s > 0; s >>= 1) {
        if (p < s) { red[p] += red[p + s]; red2[p] += red2[p + s]; }
        __syncthreads();
    }
    if (p == 0) g_S[cell] = red2[0] / red[0];
}

// One thread per batch element. phi row = 20 floats = 5 x float4 (80B aligned).
__global__ void __launch_bounds__(256)
main_kernel(const float* __restrict__ phi,
            const float* __restrict__ w,
            float* __restrict__ out) {
    const int b = blockIdx.x * blockDim.x + threadIdx.x;
    if (b >= B_TOTAL) return;

    const float w0 = __ldg(&w[0]), w1 = __ldg(&w[1]), w2 = __ldg(&w[2]);
    const float w3 = __ldg(&w[3]), w4 = __ldg(&w[4]), w5 = __ldg(&w[5]);

    const float4* ph = (const float4*)(phi + (size_t)b * 20);
    const float4 a0 = ph[0];  // phi[b,0,0..3]
    const float4 a1 = ph[1];  // phi[b,0,4..7]
    const float4 a2 = ph[2];  // phi[b,0,8..9], phi[b,1,0..1]
    const float4 a3 = ph[3];  // phi[b,1,2..5]
    const float4 a4 = ph[4];  // phi[b,1,6..9]

    // pr for t=0 and t=1 (feats are first 6 of each row of 10)
    const float pr0 = a0.x * w0 + a0.y * w1 + a0.z * w2 + a0.w * w3
                    + a1.x * w4 + a1.y * w5;
    const float pr1 = a2.z * w0 + a2.w * w1 + a3.x * w2 + a3.y * w3
                    + a3.z * w4 + a3.w * w5;

    // coords: row t=0 -> [6]=xs, [7]=ys, [8]=xe, [9]=ye
    const int is0 = (int)a1.z * Y_DIM + (int)a1.w;
    const int ie0 = (int)a2.x * Y_DIM + (int)a2.y;
    const int is1 = (int)a4.x * Y_DIM + (int)a4.y;
    const int ie1 = (int)a4.z * Y_DIM + (int)a4.w;

    const float d0 = pr0 + (g_S[ie0] - g_S[is0]);
    const float d1 = pr1 + (g_S[ie1] - g_S[is1]);

    const float diff = d0 - d1;
    out[2 * b + 0] = 1.0f / (1.0f + expf(-diff));
    out[2 * b + 1] = 1.0f / (1.0f + expf(diff));
}

extern "C" void kernel_launch(void* const* d_in, const int* in_sizes, int n_in,
                              void* d_out, int out_size) {
    const float* phi  = (const float*)d_in[0];   // (32768, 2, 10)
    const float* succ = (const float*)d_in[1];   // (128, 30, 30, 6)
    const float* w    = (const float*)d_in[2];   // (6,)
    float* out = (float*)d_out;                  // (32768, 2, 1)

    precompute_S_kernel<<<CELLS, P_DIM>>>(succ, w);
    main_kernel<<<(B_TOTAL + 255) / 256, 256>>>(phi, w, out);
}

// round 2
// speedup vs baseline: 1.2007x; 1.2007x over previous
#include <cuda_runtime.h>
#include <math.h>

#define B_TOTAL 32768
#define P_DIM   128
#define X_DIM   30
#define Y_DIM   30
#define F_DIM   6
#define CELLS   (X_DIM * Y_DIM)        // 900
#define CELLS_PER_BLK 4
#define PRE_BLOCKS (CELLS / CELLS_PER_BLK)  // 225

// Precomputed softmax-weighted value per grid cell.
__device__ float g_S[CELLS];

// 225 blocks x 128 threads. Block handles 4 consecutive cells; thread = p.
// Each thread loads 6 aligned float4 (24 floats = 4 cells x 6 feats).
__global__ void __launch_bounds__(P_DIM)
precompute_S_kernel(const float* __restrict__ succ,
                    const float* __restrict__ w) {
    const int p    = threadIdx.x;
    const int lane = p & 31;
    const int warp = p >> 5;
    const int cell0 = blockIdx.x * CELLS_PER_BLK;

    const float w0 = __ldg(&w[0]), w1 = __ldg(&w[1]), w2 = __ldg(&w[2]);
    const float w3 = __ldg(&w[3]), w4 = __ldg(&w[4]), w5 = __ldg(&w[5]);

    // byte offset = p*21600 + blockIdx.x*96 : both multiples of 16 -> float4 ok
    const float4* base =
        (const float4*)(succ + (size_t)p * (CELLS * F_DIM) + (size_t)cell0 * F_DIM);
    const float4 q0 = base[0], q1 = base[1], q2 = base[2];
    const float4 q3 = base[3], q4 = base[4], q5 = base[5];

    float v[CELLS_PER_BLK];
    v[0] = q0.x*w0 + q0.y*w1 + q0.z*w2 + q0.w*w3 + q1.x*w4 + q1.y*w5;
    v[1] = q1.z*w0 + q1.w*w1 + q2.x*w2 + q2.y*w3 + q2.z*w4 + q2.w*w5;
    v[2] = q3.x*w0 + q3.y*w1 + q3.z*w2 + q3.w*w3 + q4.x*w4 + q4.y*w5;
    v[3] = q4.z*w0 + q4.w*w1 + q5.x*w2 + q5.y*w3 + q5.z*w4 + q5.w*w5;

    float x[CELLS_PER_BLK];
#pragma unroll
    for (int j = 0; j < CELLS_PER_BLK; ++j) x[j] = v[j] / 0.001f;  // match vs / T

    // ---- warp max, then 4-warp combine via smem ----
    __shared__ float smax[CELLS_PER_BLK][4];
    float m[CELLS_PER_BLK];
#pragma unroll
    for (int j = 0; j < CELLS_PER_BLK; ++j) {
        float mm = x[j];
#pragma unroll
        for (int s = 16; s > 0; s >>= 1)
            mm = fmaxf(mm, __shfl_xor_sync(0xFFFFFFFFu, mm, s));
        m[j] = mm;
    }
    if (lane == 0) {
#pragma unroll
        for (int j = 0; j < CELLS_PER_BLK; ++j) smax[j][warp] = m[j];
    }
    __syncthreads();

    float mx[CELLS_PER_BLK];
#pragma unroll
    for (int j = 0; j < CELLS_PER_BLK; ++j)
        mx[j] = fmaxf(fmaxf(smax[j][0], smax[j][1]),
                      fmaxf(smax[j][2], smax[j][3]));

    // ---- exp + dual sum reduction ----
    __shared__ float ssum[CELLS_PER_BLK][4][2];
#pragma unroll
    for (int j = 0; j < CELLS_PER_BLK; ++j) {
        float e  = expf(x[j] - mx[j]);
        float ev = e * v[j];
#pragma unroll
        for (int s = 16; s > 0; s >>= 1) {
            e  += __shfl_xor_sync(0xFFFFFFFFu, e,  s);
            ev += __shfl_xor_sync(0xFFFFFFFFu, ev, s);
        }
        if (lane == 0) { ssum[j][warp][0] = e; ssum[j][warp][1] = ev; }
    }
    __syncthreads();

    if (p < CELLS_PER_BLK) {
        const int j = p;
        float se  = ssum[j][0][0] + ssum[j][1][0] + ssum[j][2][0] + ssum[j][3][0];
        float sev = ssum[j][0][1] + ssum[j][1][1] + ssum[j][2][1] + ssum[j][3][1];
        g_S[cell0 + j] = sev / se;
    }
}

// One thread per batch element. S-table staged in shared memory (3.6KB),
// staging LDGs overlap the phi float4 DRAM loads.
__global__ void __launch_bounds__(256)
main_kernel(const float* __restrict__ phi,
            const float* __restrict__ w,
            float* __restrict__ out) {
    __shared__ float sS[CELLS];

    const int b = blockIdx.x * blockDim.x + threadIdx.x;

    // Issue phi loads first (independent of staging loop).
    const float4* ph = (const float4*)(phi + (size_t)b * 20);
    const float4 a0 = ph[0];
    const float4 a1 = ph[1];
    const float4 a2 = ph[2];
    const float4 a3 = ph[3];
    const float4 a4 = ph[4];

    const float w0 = __ldg(&w[0]), w1 = __ldg(&w[1]), w2 = __ldg(&w[2]);
    const float w3 = __ldg(&w[3]), w4 = __ldg(&w[4]), w5 = __ldg(&w[5]);

    // Stage S into smem (coalesced, L2-resident after kernel 1).
#pragma unroll
    for (int i = threadIdx.x; i < CELLS; i += 256) sS[i] = g_S[i];
    __syncthreads();

    const float pr0 = a0.x*w0 + a0.y*w1 + a0.z*w2 + a0.w*w3 + a1.x*w4 + a1.y*w5;
    const float pr1 = a2.z*w0 + a2.w*w1 + a3.x*w2 + a3.y*w3 + a3.z*w4 + a3.w*w5;

    const int is0 = (int)a1.z * Y_DIM + (int)a1.w;
    const int ie0 = (int)a2.x * Y_DIM + (int)a2.y;
    const int is1 = (int)a4.x * Y_DIM + (int)a4.y;
    const int ie1 = (int)a4.z * Y_DIM + (int)a4.w;

    const float d0 = pr0 + (sS[ie0] - sS[is0]);
    const float d1 = pr1 + (sS[ie1] - sS[is1]);

    const float diff = d0 - d1;
    out[2*b + 0] = 1.0f / (1.0f + expf(-diff));
    out[2*b + 1] = 1.0f / (1.0f + expf( diff));
}

extern "C" void kernel_launch(void* const* d_in, const int* in_sizes, int n_in,
                              void* d_out, int out_size) {
    const float* phi  = (const float*)d_in[0];   // (32768, 2, 10)
    const float* succ = (const float*)d_in[1];   // (128, 30, 30, 6)
    const float* w    = (const float*)d_in[2];   // (6,)
    float* out = (float*)d_out;                  // (32768, 2, 1)

    precompute_S_kernel<<<PRE_BLOCKS, P_DIM>>>(succ, w);
    main_kernel<<<B_TOTAL / 256, 256>>>(phi, w, out);
}